// round 7
// baseline (speedup 1.0000x reference)
#include <cuda_runtime.h>
#include <cuda_fp16.h>
#include <cstdint>

// SoftVectorQuantizer R6: fp16 HMMA flash-style, 2 CTAs/SM (TILE_M=64).
// w = exp2(S - log2e*||e||^2), S = (2log2e*z).e ; z_soft = (W E)/rowsum(W)

#define D 256
#define KTOT 1024
#define TILE_M 64
#define KC 64
#define NCH 16
#define THREADS 256
#define SCLF 2.8853900817779268f
#define LOG2E 1.4426950408889634f

// smem layout (bytes). Post-loop scratch overlays the W tile (disjoint use).
#define OFF_CE   0            // 4KB ce
#define OFF_W    4096         // 8KB W tile [64][128B] swizzled
#define OFF_DENP OFF_W        // 4KB denom partials [64][16] (post-loop)
#define OFF_DEN  (OFF_W+4096) // 256B
#define OFF_RED  (OFF_W+4352) // 32B
#define OFF_Z    12288        // 32KB Z f16: 4 blocks [64][128B] swizzled
#define OFF_EB   45056        // 2 x 32KB E bufs: 4 blocks [64][128B]
#define SMEM_TOTAL (OFF_EB + 2*32768)   // 109824 (~107.3KB) -> 2 CTAs/SM

#define SWZ128(o) ((o) ^ (((o) >> 3) & 0x70))

__device__ __forceinline__ uint32_t smem_u32(const void* p){
    uint32_t a; asm("{ .reg .u64 t; cvta.to.shared.u64 t, %1; cvt.u32.u64 %0, t; }":"=r"(a):"l"(p)); return a;
}
__device__ __forceinline__ float ex2(float x){ float y; asm("ex2.approx.ftz.f32 %0,%1;":"=f"(y):"f"(x)); return y; }

#define CPA16(d,s) asm volatile("cp.async.cg.shared.global [%0], [%1], 16;"::"r"(d),"l"(s):"memory")
#define CPA_COMMIT() asm volatile("cp.async.commit_group;":::"memory")
#define CPA_WAIT1() asm volatile("cp.async.wait_group 1;":::"memory")
#define CPA_WAIT0() asm volatile("cp.async.wait_group 0;":::"memory")

#define LDSM4(r,a) asm volatile("ldmatrix.sync.aligned.m8n8.x4.shared.b16 {%0,%1,%2,%3}, [%4];" \
    :"=r"((r)[0]),"=r"((r)[1]),"=r"((r)[2]),"=r"((r)[3]):"r"(a))
#define LDSM4T(r,a) asm volatile("ldmatrix.sync.aligned.m8n8.x4.trans.shared.b16 {%0,%1,%2,%3}, [%4];" \
    :"=r"((r)[0]),"=r"((r)[1]),"=r"((r)[2]),"=r"((r)[3]):"r"(a))

#define MMA(dd,aa,b0,b1) asm volatile( \
    "mma.sync.aligned.m16n8k16.row.col.f32.f16.f16.f32 {%0,%1,%2,%3},{%4,%5,%6,%7},{%8,%9},{%0,%1,%2,%3};" \
    : "+f"((dd)[0]),"+f"((dd)[1]),"+f"((dd)[2]),"+f"((dd)[3]) \
    : "r"((aa)[0]),"r"((aa)[1]),"r"((aa)[2]),"r"((aa)[3]),"r"(b0),"r"(b1))

__device__ __align__(16) __half g_eh[KTOT*D];
__device__ float g_ce2[KTOT];
__device__ float g_block_loss[2048];

__global__ void prep_cb(const float* __restrict__ cb){
    int k=blockIdx.x, d=threadIdx.x;
    float v=cb[k*D+d];
    g_eh[k*D+d]=__float2half(v);
    __shared__ float sh[256];
    sh[d]=v*v; __syncthreads();
    for(int o=128;o>0;o>>=1){ if(d<o) sh[d]+=sh[d+o]; __syncthreads(); }
    if(d==0) g_ce2[k]=sh[0]*LOG2E;
}

// 32KB chunk (64 codes x 256 dims f16) -> 4 swizzled [64][128B] blocks
__device__ __forceinline__ void load_chunk(uint32_t sb,int ch,int buf,int tid){
    const char* g=(const char*)g_eh + (size_t)ch*KC*D*2;
    uint32_t eb=sb+OFF_EB+buf*32768;
    #pragma unroll
    for(int i=0;i<8;i++){
        int u=i*THREADS+tid, row=u>>5, un=u&31;
        uint32_t dst=eb+(un>>3)*8192+SWZ128((uint32_t)(row*128+(un&7)*16));
        CPA16(dst, g+(size_t)row*512+un*16);
    }
}

extern __shared__ char smem[];

__global__ void __launch_bounds__(THREADS,2) svq_hmma(
    const float* __restrict__ z, float* __restrict__ out)
{
    uint32_t sb=smem_u32(smem);
    int tid=threadIdx.x, wid=tid>>5, t=tid&31;
    int mg=wid>>2, ng=wid&3;
    size_t rowBase=(size_t)blockIdx.x*TILE_M;

    load_chunk(sb,0,0,tid); CPA_COMMIT();
    load_chunk(sb,1,1,tid); CPA_COMMIT();

    float* sCE=(float*)(smem+OFF_CE);
    for(int i=tid;i<KTOT;i+=THREADS) sCE[i]=g_ce2[i];

    { // stage Z tile -> f16 * 2log2e, 4 swizzled [64][128B] blocks
        const float4* zg=(const float4*)(z+rowBase*D);
        #pragma unroll
        for(int it=0;it<8;it++){
            int idx=it*THREADS+tid, r=idx>>5, q=idx&31;
            float4 a=zg[(size_t)r*64+q*2], b=zg[(size_t)r*64+q*2+1];
            __half2 h0=__floats2half2_rn(a.x*SCLF,a.y*SCLF), h1=__floats2half2_rn(a.z*SCLF,a.w*SCLF);
            __half2 h2=__floats2half2_rn(b.x*SCLF,b.y*SCLF), h3=__floats2half2_rn(b.z*SCLF,b.w*SCLF);
            uint4 u; u.x=*(uint32_t*)&h0; u.y=*(uint32_t*)&h1; u.z=*(uint32_t*)&h2; u.w=*(uint32_t*)&h3;
            *(uint4*)(smem+OFF_Z+(q>>3)*8192+SWZ128((uint32_t)(r*128+(q&7)*16)))=u;
        }
    }

    // ldmatrix address components (swizzled layout: row*128 + (col ^ ((row&7)<<4)))
    const uint32_t xv=(uint32_t)(t&7)<<4;
    const uint32_t c0=(uint32_t)(t>>4)<<4;
    uint32_t cs[4];
    #pragma unroll
    for(int k=0;k<4;k++) cs[k]=(c0+k*32)^xv;

    const uint32_t zA0=sb+OFF_Z+(uint32_t)(32*mg+(t&15))*128;
    const uint32_t zA1=zA0+16*128;
    const uint32_t wA0=sb+OFF_W+(uint32_t)(32*mg+(t&15))*128;
    const uint32_t wA1=wA0+16*128;
    const uint32_t xw=(uint32_t)(t>>2)<<4;

    float acc2[2][8][4]; float den[2][2]={{0.f,0.f},{0.f,0.f}};
    #pragma unroll
    for(int mi=0;mi<2;mi++)
        #pragma unroll
        for(int j=0;j<8;j++)
            #pragma unroll
            for(int q=0;q<4;q++) acc2[mi][j][q]=0.f;

    #pragma unroll 1
    for(int ch=0;ch<NCH;ch++){
        if(ch<NCH-1) CPA_WAIT1(); else CPA_WAIT0();
        __syncthreads();
        const uint32_t eb=sb+OFF_EB+(uint32_t)(ch&1)*32768;
        const uint32_t eB1=eb+(uint32_t)(16*ng+(t&15))*128;

        // ---- GEMM1: S[m32 x n16] ----
        float acc1[2][2][4];
        #pragma unroll
        for(int mi=0;mi<2;mi++)
            #pragma unroll
            for(int ni=0;ni<2;ni++)
                #pragma unroll
                for(int q=0;q<4;q++) acc1[mi][ni][q]=0.f;
        #pragma unroll
        for(int ks=0;ks<16;ks++){
            uint32_t a0[4],a1[4],b[4];
            uint32_t blk=(uint32_t)(ks>>2)*8192, cc=cs[ks&3];
            LDSM4(a0, zA0+blk+cc);
            LDSM4(a1, zA1+blk+cc);
            LDSM4(b,  eB1+blk+cc);
            MMA(acc1[0][0],a0,b[0],b[2]); MMA(acc1[0][1],a0,b[1],b[3]);
            MMA(acc1[1][0],a1,b[0],b[2]); MMA(acc1[1][1],a1,b[1],b[3]);
        }

        // ---- epilogue: w=ex2(S-ce), denom partials, pack W ----
        const float* ce=sCE+ch*64;
        #pragma unroll
        for(int mi=0;mi<2;mi++){
            uint32_t r0=(uint32_t)(32*mg+16*mi+(t>>2));
            #pragma unroll
            for(int ni=0;ni<2;ni++){
                int col=16*ng+ni*8+(t&3)*2;
                float w0=ex2(acc1[mi][ni][0]-ce[col]);
                float w1=ex2(acc1[mi][ni][1]-ce[col+1]);
                float w2=ex2(acc1[mi][ni][2]-ce[col]);
                float w3=ex2(acc1[mi][ni][3]-ce[col+1]);
                den[mi][0]+=w0+w1; den[mi][1]+=w2+w3;
                __half2 p0=__floats2half2_rn(w0,w1), p1=__floats2half2_rn(w2,w3);
                uint32_t cw=((uint32_t)(col*2))^xw;
                *(uint32_t*)(smem+OFF_W+r0*128+cw)=*(uint32_t*)&p0;
                *(uint32_t*)(smem+OFF_W+(r0+8)*128+cw)=*(uint32_t*)&p1;
            }
        }
        __syncthreads();

        // ---- GEMM2: acc2[m32 x n64] += W[m32 x k64] * E[k64 x n64(ng)] ----
        #pragma unroll
        for(int ks=0;ks<4;ks++){
            uint32_t a0[4],a1[4];
            LDSM4(a0, wA0+cs[ks]);
            LDSM4(a1, wA1+cs[ks]);
            uint32_t eRow=eb+(uint32_t)ng*8192+(uint32_t)(ks*16+(t&15))*128;
            #pragma unroll
            for(int nt=0;nt<4;nt++){
                uint32_t bt[4];
                LDSM4T(bt, eRow+cs[nt]);
                MMA(acc2[0][nt*2],  a0,bt[0],bt[1]); MMA(acc2[0][nt*2+1],a0,bt[2],bt[3]);
                MMA(acc2[1][nt*2],  a1,bt[0],bt[1]); MMA(acc2[1][nt*2+1],a1,bt[2],bt[3]);
            }
        }
        __syncthreads();   // E buffer + W reads done before refill/overwrite
        if(ch<NCH-2){ load_chunk(sb,ch+2,ch&1,tid); CPA_COMMIT(); }
    }

    // ---- denominator reduce (fixed order; DENP overlays W, safe post-sync) ----
    float* dP=(float*)(smem+OFF_DENP);
    #pragma unroll
    for(int mi=0;mi<2;mi++){
        int rr=32*mg+16*mi+(t>>2);
        dP[rr*16+ng*4+(t&3)]=den[mi][0];
        dP[(rr+8)*16+ng*4+(t&3)]=den[mi][1];
    }
    __syncthreads();
    float* dF=(float*)(smem+OFF_DEN);
    if(tid<TILE_M){
        float s=0.f;
        #pragma unroll
        for(int j=0;j<16;j++) s+=dP[tid*16+j];
        dF[tid]=s;
    }
    __syncthreads();

    // ---- normalize, write out, loss vs fp32 z ----
    float lsum=0.f;
    #pragma unroll
    for(int mi=0;mi<2;mi++){
        int r0=32*mg+16*mi+(t>>2);
        float inv0=1.f/dF[r0], inv1=1.f/dF[r0+8];
        size_t g0=(rowBase+r0)*D, g1=g0+8*(size_t)D;
        #pragma unroll
        for(int j=0;j<8;j++){
            int dc=64*ng+j*8+(t&3)*2;
            float ox0=acc2[mi][j][0]*inv0, oy0=acc2[mi][j][1]*inv0;
            float ox1=acc2[mi][j][2]*inv1, oy1=acc2[mi][j][3]*inv1;
            float2 z0=*(const float2*)(z+g0+dc);
            float2 z1=*(const float2*)(z+g1+dc);
            float d0=ox0-z0.x, d1=oy0-z0.y, d2=ox1-z1.x, d3=oy1-z1.y;
            lsum+=d0*d0+d1*d1+d2*d2+d3*d3;
            *(float2*)(out+g0+dc)=make_float2(ox0,oy0);
            *(float2*)(out+g1+dc)=make_float2(ox1,oy1);
        }
    }
    #pragma unroll
    for(int o=16;o>0;o>>=1) lsum+=__shfl_down_sync(0xffffffffu,lsum,o);
    float* sRed=(float*)(smem+OFF_RED);
    if(t==0) sRed[wid]=lsum;
    __syncthreads();
    if(tid==0){
        float s=0.f;
        #pragma unroll
        for(int w=0;w<8;w++) s+=sRed[w];
        g_block_loss[blockIdx.x]=s;
    }
}

__global__ void loss_finalize(float* __restrict__ out,int nblocks,float inv_nd,int li){
    __shared__ float sh[256];
    int tid=threadIdx.x; float s=0.f;
    for(int i=tid;i<nblocks;i+=256) s+=g_block_loss[i];
    sh[tid]=s; __syncthreads();
    for(int o=128;o>0;o>>=1){ if(tid<o) sh[tid]+=sh[tid+o]; __syncthreads(); }
    if(tid==0) out[li]=sh[0]*inv_nd;
}

extern "C" void kernel_launch(void* const* d_in,const int* in_sizes,int n_in,
                              void* d_out,int out_size){
    const float* z=(const float*)d_in[0];
    const float* cb=(const float*)d_in[1];
    int sz0=in_sizes[0], sz1=in_sizes[1];
    if(sz0<sz1){ const float* tp=z; z=cb; cb=tp; int ts=sz0; sz0=sz1; sz1=ts; }
    float* out=(float*)d_out;
    int nrows=sz0/D, nblocks=nrows/TILE_M;

    cudaFuncSetAttribute(svq_hmma, cudaFuncAttributeMaxDynamicSharedMemorySize, SMEM_TOTAL);
    prep_cb<<<KTOT,256>>>(cb);
    svq_hmma<<<nblocks,THREADS,SMEM_TOTAL>>>(z,out);
    loss_finalize<<<1,256>>>(out,nblocks,1.0f/((float)nrows*(float)D),out_size-1);
}

// round 8
// speedup vs baseline: 1.1221x; 1.1221x over previous
#include <cuda_runtime.h>
#include <cuda_fp16.h>
#include <cstdint>

// SoftVectorQuantizer R7: HMMA flash, fat warp tiles (8 warps), f16-acc GEMM1,
// h2-exp epilogue. w = exp2(S - log2e||e||^2), S = (2log2e z).e
// z_soft = (W E)/rowsum(W); loss = mean((z_soft - z)^2) vs fp32 z.

#define D 256
#define KTOT 1024
#define TILE_M 128
#define KC 64
#define NCH 16
#define THREADS 256
#define SCLF 2.8853900817779268f
#define LOG2E 1.4426950408889634f

// smem (bytes)
#define OFF_CE   0                 // 2KB half ce
#define OFF_W    2048              // 16KB W [128][128B] swizzled
#define OFF_DENP OFF_W             // overlay: 4KB den partials [128][8]
#define OFF_DEN  (OFF_W+4096)      // 512B
#define OFF_RED  (OFF_W+4608)      // 32B
#define OFF_Z    18432             // 64KB Z f16: 4 blocks [128][128B]
#define OFF_EB   83968             // 2 x 32KB E bufs: 4 blocks [64][128B]
#define SMEM_TOTAL (OFF_EB + 2*32768)   // 149504 (~146KB)

#define SWZ128(o) ((o) ^ (((o) >> 3) & 0x70))

__device__ __forceinline__ uint32_t smem_u32(const void* p){
    uint32_t a; asm("{ .reg .u64 t; cvta.to.shared.u64 t, %1; cvt.u32.u64 %0, t; }":"=r"(a):"l"(p)); return a;
}
__device__ __forceinline__ uint32_t h2ex2(uint32_t x){
    uint32_t y; asm("ex2.approx.f16x2 %0, %1;":"=r"(y):"r"(x)); return y;
}

#define CPA16(d,s) asm volatile("cp.async.cg.shared.global [%0], [%1], 16;"::"r"(d),"l"(s):"memory")
#define CPA_COMMIT() asm volatile("cp.async.commit_group;":::"memory")
#define CPA_WAIT1() asm volatile("cp.async.wait_group 1;":::"memory")
#define CPA_WAIT0() asm volatile("cp.async.wait_group 0;":::"memory")

#define LDSM4(r,a) asm volatile("ldmatrix.sync.aligned.m8n8.x4.shared.b16 {%0,%1,%2,%3}, [%4];" \
    :"=r"((r)[0]),"=r"((r)[1]),"=r"((r)[2]),"=r"((r)[3]):"r"(a))
#define LDSM4T(r,a) asm volatile("ldmatrix.sync.aligned.m8n8.x4.trans.shared.b16 {%0,%1,%2,%3}, [%4];" \
    :"=r"((r)[0]),"=r"((r)[1]),"=r"((r)[2]),"=r"((r)[3]):"r"(a))

// f32-acc HMMA (GEMM2)
#define MMA(dd,aa,b0,b1) asm volatile( \
    "mma.sync.aligned.m16n8k16.row.col.f32.f16.f16.f32 {%0,%1,%2,%3},{%4,%5,%6,%7},{%8,%9},{%0,%1,%2,%3};" \
    : "+f"((dd)[0]),"+f"((dd)[1]),"+f"((dd)[2]),"+f"((dd)[3]) \
    : "r"((aa)[0]),"r"((aa)[1]),"r"((aa)[2]),"r"((aa)[3]),"r"(b0),"r"(b1))
// f16-acc HMMA (GEMM1)
#define MMAH(dd,aa,b0,b1) asm volatile( \
    "mma.sync.aligned.m16n8k16.row.col.f16.f16.f16.f16 {%0,%1},{%2,%3,%4,%5},{%6,%7},{%0,%1};" \
    : "+r"((dd)[0]),"+r"((dd)[1]) \
    : "r"((aa)[0]),"r"((aa)[1]),"r"((aa)[2]),"r"((aa)[3]),"r"(b0),"r"(b1))

__device__ __align__(16) __half g_eh[KTOT*D];
__device__ float g_ce2[KTOT];
__device__ float g_block_loss[1024];

__global__ void prep_cb(const float* __restrict__ cb){
    int k=blockIdx.x, d=threadIdx.x;
    float v=cb[k*D+d];
    g_eh[k*D+d]=__float2half(v);
    __shared__ float sh[256];
    sh[d]=v*v; __syncthreads();
    for(int o=128;o>0;o>>=1){ if(d<o) sh[d]+=sh[d+o]; __syncthreads(); }
    if(d==0) g_ce2[k]=sh[0]*LOG2E;
}

// 32KB chunk (64 codes x 256 dims f16) -> 4 swizzled [64][128B] blocks
__device__ __forceinline__ void load_chunk(uint32_t sb,int ch,int buf,int tid){
    const char* g=(const char*)g_eh + (size_t)ch*KC*D*2;
    uint32_t eb=sb+OFF_EB+buf*32768;
    #pragma unroll
    for(int i=0;i<8;i++){
        int u=i*THREADS+tid, row=u>>5, un=u&31;
        uint32_t dst=eb+(un>>3)*8192+SWZ128((uint32_t)(row*128+(un&7)*16));
        CPA16(dst, g+(size_t)row*512+un*16);
    }
}

extern __shared__ char smem[];

__global__ void __launch_bounds__(THREADS,1) svq_hmma(
    const float* __restrict__ z, float* __restrict__ out)
{
    uint32_t sb=smem_u32(smem);
    int tid=threadIdx.x, wid=tid>>5, t=tid&31;
    int mg=wid>>1, ng1=wid&1;      // GEMM1 grid 4x2 (m32 x n32)
    int mg2=wid>>2, ng2=wid&3;     // GEMM2 grid 2x4 (m64 x n64)
    size_t rowBase=(size_t)blockIdx.x*TILE_M;

    load_chunk(sb,0,0,tid); CPA_COMMIT();
    load_chunk(sb,1,1,tid); CPA_COMMIT();

    __half* sCE=(__half*)(smem+OFF_CE);
    for(int i=tid;i<KTOT;i+=THREADS) sCE[i]=__float2half(g_ce2[i]);

    { // stage Z -> f16 * 2log2e, 4 swizzled [128][128B] blocks (stride 16384)
        const float4* zg=(const float4*)(z+rowBase*D);
        #pragma unroll
        for(int it=0;it<16;it++){
            int idx=it*THREADS+tid, r=idx>>5, q=idx&31;
            float4 a=zg[(size_t)r*64+q*2], b=zg[(size_t)r*64+q*2+1];
            __half2 h0=__floats2half2_rn(a.x*SCLF,a.y*SCLF), h1=__floats2half2_rn(a.z*SCLF,a.w*SCLF);
            __half2 h2=__floats2half2_rn(b.x*SCLF,b.y*SCLF), h3=__floats2half2_rn(b.z*SCLF,b.w*SCLF);
            uint4 u; u.x=*(uint32_t*)&h0; u.y=*(uint32_t*)&h1; u.z=*(uint32_t*)&h2; u.w=*(uint32_t*)&h3;
            *(uint4*)(smem+OFF_Z+(q>>3)*16384+SWZ128((uint32_t)(r*128+(q&7)*16)))=u;
        }
    }

    const uint32_t xv=(uint32_t)(t&7)<<4;
    const uint32_t c0=(uint32_t)(t>>4)<<4;
    uint32_t cs[4];
    #pragma unroll
    for(int k=0;k<4;k++) cs[k]=(c0+k*32)^xv;

    const uint32_t zA0=sb+OFF_Z+(uint32_t)(32*mg+(t&15))*128;   // +16384/blk
    const uint32_t xw=(uint32_t)(t>>2)<<4;

    float acc2[4][8][4];
    #pragma unroll
    for(int mi=0;mi<4;mi++)
        #pragma unroll
        for(int j=0;j<8;j++)
            #pragma unroll
            for(int q=0;q<4;q++) acc2[mi][j][q]=0.f;
    float den[4]={0.f,0.f,0.f,0.f};

    #pragma unroll 1
    for(int ch=0;ch<NCH;ch++){
        if(ch<NCH-1) CPA_WAIT1(); else CPA_WAIT0();
        __syncthreads();
        const uint32_t eb=sb+OFF_EB+(uint32_t)(ch&1)*32768;
        const uint32_t eB0=eb+(uint32_t)(32*ng1+(t&15))*128;    // +8192/blk

        // ---- GEMM1: S[m32 x n32], f16 acc ----
        uint32_t acc1[2][4][2];
        #pragma unroll
        for(int mi=0;mi<2;mi++)
            #pragma unroll
            for(int nj=0;nj<4;nj++){ acc1[mi][nj][0]=0u; acc1[mi][nj][1]=0u; }
        #pragma unroll
        for(int ks=0;ks<16;ks++){
            uint32_t a0[4],a1[4],b0[4],b1[4];
            uint32_t zblk=(uint32_t)(ks>>2)*16384, eblk=(uint32_t)(ks>>2)*8192, cc=cs[ks&3];
            LDSM4(a0, zA0+zblk+cc);
            LDSM4(a1, zA0+2048+zblk+cc);
            LDSM4(b0, eB0+eblk+cc);
            LDSM4(b1, eB0+2048+eblk+cc);
            MMAH(acc1[0][0],a0,b0[0],b0[2]); MMAH(acc1[0][1],a0,b0[1],b0[3]);
            MMAH(acc1[0][2],a0,b1[0],b1[2]); MMAH(acc1[0][3],a0,b1[1],b1[3]);
            MMAH(acc1[1][0],a1,b0[0],b0[2]); MMAH(acc1[1][1],a1,b0[1],b0[3]);
            MMAH(acc1[1][2],a1,b1[0],b1[2]); MMAH(acc1[1][3],a1,b1[1],b1[3]);
        }

        // ---- epilogue: w = ex2(S - ce) in half2, den partials, store W ----
        const __half2* ceh=(const __half2*)(smem+OFF_CE)+(ch*32)+(16*ng1)+(t&3);
        #pragma unroll
        for(int mi=0;mi<2;mi++){
            uint32_t r0=(uint32_t)(32*mg+16*mi+(t>>2));
            #pragma unroll
            for(int nj=0;nj<4;nj++){
                __half2 ce2v=ceh[nj*4];
                uint32_t s0=acc1[mi][nj][0], s1=acc1[mi][nj][1];
                __half2 d0=__hsub2(*(__half2*)&s0,ce2v), d1=__hsub2(*(__half2*)&s1,ce2v);
                uint32_t w0=h2ex2(*(uint32_t*)&d0), w1=h2ex2(*(uint32_t*)&d1);
                float2 f0=__half22float2(*(__half2*)&w0), f1=__half22float2(*(__half2*)&w1);
                den[mi*2+0]+=f0.x+f0.y; den[mi*2+1]+=f1.x+f1.y;
                uint32_t cw=((uint32_t)((32*ng1+nj*8+(t&3)*2)*2))^xw;
                *(uint32_t*)(smem+OFF_W+r0*128+cw)=w0;
                *(uint32_t*)(smem+OFF_W+(r0+8)*128+cw)=w1;
            }
        }
        __syncthreads();

        // ---- GEMM2: acc2[m64 x n64] += W[m64 x k64] * E^T ----
        #pragma unroll
        for(int ks=0;ks<4;ks++){
            uint32_t a[4][4];
            #pragma unroll
            for(int q=0;q<4;q++)
                LDSM4(a[q], sb+OFF_W+(uint32_t)(64*mg2+16*q+(t&15))*128+cs[ks]);
            uint32_t eT=eb+(uint32_t)ng2*8192+(uint32_t)(ks*16+(t&15))*128;
            #pragma unroll
            for(int nt=0;nt<4;nt++){
                uint32_t bt[4];
                LDSM4T(bt, eT+cs[nt]);
                #pragma unroll
                for(int mi=0;mi<4;mi++){
                    MMA(acc2[mi][nt*2],  a[mi],bt[0],bt[1]);
                    MMA(acc2[mi][nt*2+1],a[mi],bt[2],bt[3]);
                }
            }
        }
        __syncthreads();   // W + E buffer reads done before refill/overwrite
        if(ch<NCH-2){ load_chunk(sb,ch+2,ch&1,tid); CPA_COMMIT(); }
    }

    // ---- denominator reduce (fixed order; overlays W post-sync) ----
    float* dP=(float*)(smem+OFF_DENP);
    #pragma unroll
    for(int mi=0;mi<2;mi++)
        #pragma unroll
        for(int rg=0;rg<2;rg++){
            int rr=32*mg+16*mi+8*rg+(t>>2);
            dP[rr*8+ng1*4+(t&3)]=den[mi*2+rg];
        }
    __syncthreads();
    float* dF=(float*)(smem+OFF_DEN);
    if(tid<TILE_M){
        float s=0.f;
        #pragma unroll
        for(int j=0;j<8;j++) s+=dP[tid*8+j];
        dF[tid]=s;
    }
    __syncthreads();

    // ---- normalize, write out, loss vs fp32 z ----
    float lsum=0.f;
    #pragma unroll
    for(int mi=0;mi<4;mi++){
        int r0=64*mg2+16*mi+(t>>2);
        float inv0=1.f/dF[r0], inv1=1.f/dF[r0+8];
        size_t g0=(rowBase+r0)*D, g1=g0+8*(size_t)D;
        #pragma unroll
        for(int j=0;j<8;j++){
            int dc=64*ng2+j*8+(t&3)*2;
            float ox0=acc2[mi][j][0]*inv0, oy0=acc2[mi][j][1]*inv0;
            float ox1=acc2[mi][j][2]*inv1, oy1=acc2[mi][j][3]*inv1;
            float2 z0=*(const float2*)(z+g0+dc);
            float2 z1=*(const float2*)(z+g1+dc);
            float d0=ox0-z0.x, d1=oy0-z0.y, d2=ox1-z1.x, d3=oy1-z1.y;
            lsum+=d0*d0+d1*d1+d2*d2+d3*d3;
            *(float2*)(out+g0+dc)=make_float2(ox0,oy0);
            *(float2*)(out+g1+dc)=make_float2(ox1,oy1);
        }
    }
    #pragma unroll
    for(int o=16;o>0;o>>=1) lsum+=__shfl_down_sync(0xffffffffu,lsum,o);
    float* sRed=(float*)(smem+OFF_RED);
    if(t==0) sRed[wid]=lsum;
    __syncthreads();
    if(tid==0){
        float s=0.f;
        #pragma unroll
        for(int w=0;w<8;w++) s+=sRed[w];
        g_block_loss[blockIdx.x]=s;
    }
}

__global__ void loss_finalize(float* __restrict__ out,int nblocks,float inv_nd,int li){
    __shared__ float sh[256];
    int tid=threadIdx.x; float s=0.f;
    for(int i=tid;i<nblocks;i+=256) s+=g_block_loss[i];
    sh[tid]=s; __syncthreads();
    for(int o=128;o>0;o>>=1){ if(tid<o) sh[tid]+=sh[tid+o]; __syncthreads(); }
    if(tid==0) out[li]=sh[0]*inv_nd;
}

extern "C" void kernel_launch(void* const* d_in,const int* in_sizes,int n_in,
                              void* d_out,int out_size){
    const float* z=(const float*)d_in[0];
    const float* cb=(const float*)d_in[1];
    int sz0=in_sizes[0], sz1=in_sizes[1];
    if(sz0<sz1){ const float* tp=z; z=cb; cb=tp; int ts=sz0; sz0=sz1; sz1=ts; }
    float* out=(float*)d_out;
    int nrows=sz0/D, nblocks=nrows/TILE_M;

    cudaFuncSetAttribute(svq_hmma, cudaFuncAttributeMaxDynamicSharedMemorySize, SMEM_TOTAL);
    prep_cb<<<KTOT,256>>>(cb);
    svq_hmma<<<nblocks,THREADS,SMEM_TOTAL>>>(z,out);
    loss_finalize<<<1,256>>>(out,nblocks,1.0f/((float)nrows*(float)D),out_size-1);
}

// round 9
// speedup vs baseline: 1.1261x; 1.0035x over previous
#include <cuda_runtime.h>
#include <cuda_fp16.h>
#include <cstdint>

// SoftVectorQuantizer R8: fat warp tiles (R7) at TILE_M=64 / 4 warps,
// 2 CTAs/SM for cross-CTA overlap of syncs/epilogue/loads.
// w = exp2(S - log2e||e||^2), S = (2log2e z).e; z_soft=(W E)/rowsum(W)

#define D 256
#define KTOT 1024
#define TILE_M 64
#define KC 64
#define NCH 16
#define THREADS 128
#define SCLF 2.8853900817779268f
#define LOG2E 1.4426950408889634f

// smem (bytes); post-loop scratch overlays W
#define OFF_CE   0               // 2KB half ce
#define OFF_W    2048            // 8KB W [64][128B] swizzled
#define OFF_DENP OFF_W           // overlay 2KB den partials [64][8]
#define OFF_DEN  (OFF_W+2048)    // 256B
#define OFF_RED  (OFF_W+2304)    // 16B
#define OFF_Z    10240           // 32KB Z f16: 4 blocks [64][128B]
#define OFF_EB   43008           // 2 x 32KB E bufs: 4 blocks [64][128B]
#define SMEM_TOTAL (OFF_EB + 2*32768)   // 108544 (~106KB) -> 2 CTAs/SM

#define SWZ128(o) ((o) ^ (((o) >> 3) & 0x70))

__device__ __forceinline__ uint32_t smem_u32(const void* p){
    uint32_t a; asm("{ .reg .u64 t; cvta.to.shared.u64 t, %1; cvt.u32.u64 %0, t; }":"=r"(a):"l"(p)); return a;
}
__device__ __forceinline__ uint32_t h2ex2(uint32_t x){
    uint32_t y; asm("ex2.approx.f16x2 %0, %1;":"=r"(y):"r"(x)); return y;
}

#define CPA16(d,s) asm volatile("cp.async.cg.shared.global [%0], [%1], 16;"::"r"(d),"l"(s):"memory")
#define CPA_COMMIT() asm volatile("cp.async.commit_group;":::"memory")
#define CPA_WAIT1() asm volatile("cp.async.wait_group 1;":::"memory")
#define CPA_WAIT0() asm volatile("cp.async.wait_group 0;":::"memory")

#define LDSM4(r,a) asm volatile("ldmatrix.sync.aligned.m8n8.x4.shared.b16 {%0,%1,%2,%3}, [%4];" \
    :"=r"((r)[0]),"=r"((r)[1]),"=r"((r)[2]),"=r"((r)[3]):"r"(a))
#define LDSM4T(r,a) asm volatile("ldmatrix.sync.aligned.m8n8.x4.trans.shared.b16 {%0,%1,%2,%3}, [%4];" \
    :"=r"((r)[0]),"=r"((r)[1]),"=r"((r)[2]),"=r"((r)[3]):"r"(a))

#define MMA(dd,aa,b0,b1) asm volatile( \
    "mma.sync.aligned.m16n8k16.row.col.f32.f16.f16.f32 {%0,%1,%2,%3},{%4,%5,%6,%7},{%8,%9},{%0,%1,%2,%3};" \
    : "+f"((dd)[0]),"+f"((dd)[1]),"+f"((dd)[2]),"+f"((dd)[3]) \
    : "r"((aa)[0]),"r"((aa)[1]),"r"((aa)[2]),"r"((aa)[3]),"r"(b0),"r"(b1))
#define MMAH(dd,aa,b0,b1) asm volatile( \
    "mma.sync.aligned.m16n8k16.row.col.f16.f16.f16.f16 {%0,%1},{%2,%3,%4,%5},{%6,%7},{%0,%1};" \
    : "+r"((dd)[0]),"+r"((dd)[1]) \
    : "r"((aa)[0]),"r"((aa)[1]),"r"((aa)[2]),"r"((aa)[3]),"r"(b0),"r"(b1))

__device__ __align__(16) __half g_eh[KTOT*D];
__device__ float g_ce2[KTOT];
__device__ float g_block_loss[2048];

__global__ void prep_cb(const float* __restrict__ cb){
    int k=blockIdx.x, d=threadIdx.x;
    float v=cb[k*D+d];
    g_eh[k*D+d]=__float2half(v);
    __shared__ float sh[256];
    sh[d]=v*v; __syncthreads();
    for(int o=128;o>0;o>>=1){ if(d<o) sh[d]+=sh[d+o]; __syncthreads(); }
    if(d==0) g_ce2[k]=sh[0]*LOG2E;
}

// 32KB chunk (64 codes x 256 dims f16) -> 4 swizzled [64][128B] blocks
__device__ __forceinline__ void load_chunk(uint32_t sb,int ch,int buf,int tid){
    const char* g=(const char*)g_eh + (size_t)ch*KC*D*2;
    uint32_t eb=sb+OFF_EB+buf*32768;
    #pragma unroll
    for(int i=0;i<16;i++){
        int u=i*THREADS+tid, row=u>>5, un=u&31;
        uint32_t dst=eb+(un>>3)*8192+SWZ128((uint32_t)(row*128+(un&7)*16));
        CPA16(dst, g+(size_t)row*512+un*16);
    }
}

extern __shared__ char smem[];

__global__ void __launch_bounds__(THREADS,2) svq_hmma(
    const float* __restrict__ z, float* __restrict__ out)
{
    uint32_t sb=smem_u32(smem);
    int tid=threadIdx.x, wid=tid>>5, t=tid&31;
    int mg=wid>>1, ng1=wid&1;      // GEMM1 grid 2x2 (m32 x n32)
    int ng2=wid;                   // GEMM2 grid 1x4 (m64 x n64)
    size_t rowBase=(size_t)blockIdx.x*TILE_M;

    load_chunk(sb,0,0,tid); CPA_COMMIT();
    load_chunk(sb,1,1,tid); CPA_COMMIT();

    __half* sCE=(__half*)(smem+OFF_CE);
    for(int i=tid;i<KTOT;i+=THREADS) sCE[i]=__float2half(g_ce2[i]);

    { // stage Z -> f16 * 2log2e, 4 swizzled [64][128B] blocks (stride 8192)
        const float4* zg=(const float4*)(z+rowBase*D);
        #pragma unroll
        for(int it=0;it<16;it++){
            int idx=it*THREADS+tid, r=idx>>5, q=idx&31;
            float4 a=zg[(size_t)r*64+q*2], b=zg[(size_t)r*64+q*2+1];
            __half2 h0=__floats2half2_rn(a.x*SCLF,a.y*SCLF), h1=__floats2half2_rn(a.z*SCLF,a.w*SCLF);
            __half2 h2=__floats2half2_rn(b.x*SCLF,b.y*SCLF), h3=__floats2half2_rn(b.z*SCLF,b.w*SCLF);
            uint4 u; u.x=*(uint32_t*)&h0; u.y=*(uint32_t*)&h1; u.z=*(uint32_t*)&h2; u.w=*(uint32_t*)&h3;
            *(uint4*)(smem+OFF_Z+(q>>3)*8192+SWZ128((uint32_t)(r*128+(q&7)*16)))=u;
        }
    }

    const uint32_t xv=(uint32_t)(t&7)<<4;
    const uint32_t c0=(uint32_t)(t>>4)<<4;
    uint32_t cs[4];
    #pragma unroll
    for(int k=0;k<4;k++) cs[k]=(c0+k*32)^xv;

    const uint32_t zA0=sb+OFF_Z+(uint32_t)(32*mg+(t&15))*128;   // +8192/blk
    const uint32_t xw=(uint32_t)(t>>2)<<4;

    float acc2[4][8][4];
    #pragma unroll
    for(int mi=0;mi<4;mi++)
        #pragma unroll
        for(int j=0;j<8;j++)
            #pragma unroll
            for(int q=0;q<4;q++) acc2[mi][j][q]=0.f;
    float den[4]={0.f,0.f,0.f,0.f};

    #pragma unroll 1
    for(int ch=0;ch<NCH;ch++){
        if(ch<NCH-1) CPA_WAIT1(); else CPA_WAIT0();
        __syncthreads();
        const uint32_t eb=sb+OFF_EB+(uint32_t)(ch&1)*32768;
        const uint32_t eB0=eb+(uint32_t)(32*ng1+(t&15))*128;    // +8192/blk

        // ---- GEMM1: S[m32 x n32], f16 acc ----
        uint32_t acc1[2][4][2];
        #pragma unroll
        for(int mi=0;mi<2;mi++)
            #pragma unroll
            for(int nj=0;nj<4;nj++){ acc1[mi][nj][0]=0u; acc1[mi][nj][1]=0u; }
        #pragma unroll
        for(int ks=0;ks<16;ks++){
            uint32_t a0[4],a1[4],b0[4],b1[4];
            uint32_t blk=(uint32_t)(ks>>2)*8192, cc=cs[ks&3];
            LDSM4(a0, zA0+blk+cc);
            LDSM4(a1, zA0+2048+blk+cc);
            LDSM4(b0, eB0+blk+cc);
            LDSM4(b1, eB0+2048+blk+cc);
            MMAH(acc1[0][0],a0,b0[0],b0[2]); MMAH(acc1[0][1],a0,b0[1],b0[3]);
            MMAH(acc1[0][2],a0,b1[0],b1[2]); MMAH(acc1[0][3],a0,b1[1],b1[3]);
            MMAH(acc1[1][0],a1,b0[0],b0[2]); MMAH(acc1[1][1],a1,b0[1],b0[3]);
            MMAH(acc1[1][2],a1,b1[0],b1[2]); MMAH(acc1[1][3],a1,b1[1],b1[3]);
        }

        // ---- epilogue: w = ex2(S - ce) in half2, den partials, store W ----
        const __half2* ceh=(const __half2*)(smem+OFF_CE)+(ch*32)+(16*ng1)+(t&3);
        #pragma unroll
        for(int mi=0;mi<2;mi++){
            uint32_t r0=(uint32_t)(32*mg+16*mi+(t>>2));
            #pragma unroll
            for(int nj=0;nj<4;nj++){
                __half2 ce2v=ceh[nj*4];
                uint32_t s0=acc1[mi][nj][0], s1=acc1[mi][nj][1];
                __half2 d0=__hsub2(*(__half2*)&s0,ce2v), d1=__hsub2(*(__half2*)&s1,ce2v);
                uint32_t w0=h2ex2(*(uint32_t*)&d0), w1=h2ex2(*(uint32_t*)&d1);
                float2 f0=__half22float2(*(__half2*)&w0), f1=__half22float2(*(__half2*)&w1);
                den[mi*2+0]+=f0.x+f0.y; den[mi*2+1]+=f1.x+f1.y;
                uint32_t cw=((uint32_t)((32*ng1+nj*8+(t&3)*2)*2))^xw;
                *(uint32_t*)(smem+OFF_W+r0*128+cw)=w0;
                *(uint32_t*)(smem+OFF_W+(r0+8)*128+cw)=w1;
            }
        }
        __syncthreads();

        // ---- GEMM2: acc2[m64 x n64] += W[m64 x k64] * E^T(block ng2) ----
        #pragma unroll
        for(int ks=0;ks<4;ks++){
            uint32_t a[4][4];
            #pragma unroll
            for(int q=0;q<4;q++)
                LDSM4(a[q], sb+OFF_W+(uint32_t)(16*q+(t&15))*128+cs[ks]);
            uint32_t eT=eb+(uint32_t)ng2*8192+(uint32_t)(ks*16+(t&15))*128;
            #pragma unroll
            for(int nt=0;nt<4;nt++){
                uint32_t bt[4];
                LDSM4T(bt, eT+cs[nt]);
                #pragma unroll
                for(int mi=0;mi<4;mi++){
                    MMA(acc2[mi][nt*2],  a[mi],bt[0],bt[1]);
                    MMA(acc2[mi][nt*2+1],a[mi],bt[2],bt[3]);
                }
            }
        }
        __syncthreads();   // W + E buffer reads done before refill/overwrite
        if(ch<NCH-2){ load_chunk(sb,ch+2,ch&1,tid); CPA_COMMIT(); }
    }

    // ---- denominator reduce (fixed order; overlays W post-sync) ----
    float* dP=(float*)(smem+OFF_DENP);
    #pragma unroll
    for(int mi=0;mi<2;mi++)
        #pragma unroll
        for(int rg=0;rg<2;rg++){
            int rr=32*mg+16*mi+8*rg+(t>>2);
            dP[rr*8+ng1*4+(t&3)]=den[mi*2+rg];
        }
    __syncthreads();
    float* dF=(float*)(smem+OFF_DEN);
    if(tid<TILE_M){
        float s=0.f;
        #pragma unroll
        for(int j=0;j<8;j++) s+=dP[tid*8+j];
        dF[tid]=s;
    }
    __syncthreads();

    // ---- normalize, write out, loss vs fp32 z ----
    float lsum=0.f;
    #pragma unroll
    for(int mi=0;mi<4;mi++){
        int r0=16*mi+(t>>2);
        float inv0=1.f/dF[r0], inv1=1.f/dF[r0+8];
        size_t g0=(rowBase+r0)*D, g1=g0+8*(size_t)D;
        #pragma unroll
        for(int j=0;j<8;j++){
            int dc=64*ng2+j*8+(t&3)*2;
            float ox0=acc2[mi][j][0]*inv0, oy0=acc2[mi][j][1]*inv0;
            float ox1=acc2[mi][j][2]*inv1, oy1=acc2[mi][j][3]*inv1;
            float2 z0=*(const float2*)(z+g0+dc);
            float2 z1=*(const float2*)(z+g1+dc);
            float d0=ox0-z0.x, d1=oy0-z0.y, d2=ox1-z1.x, d3=oy1-z1.y;
            lsum+=d0*d0+d1*d1+d2*d2+d3*d3;
            *(float2*)(out+g0+dc)=make_float2(ox0,oy0);
            *(float2*)(out+g1+dc)=make_float2(ox1,oy1);
        }
    }
    #pragma unroll
    for(int o=16;o>0;o>>=1) lsum+=__shfl_down_sync(0xffffffffu,lsum,o);
    float* sRed=(float*)(smem+OFF_RED);
    if(t==0) sRed[wid]=lsum;
    __syncthreads();
    if(tid==0){
        float s=0.f;
        #pragma unroll
        for(int w=0;w<4;w++) s+=sRed[w];
        g_block_loss[blockIdx.x]=s;
    }
}

__global__ void loss_finalize(float* __restrict__ out,int nblocks,float inv_nd,int li){
    __shared__ float sh[256];
    int tid=threadIdx.x; float s=0.f;
    for(int i=tid;i<nblocks;i+=256) s+=g_block_loss[i];
    sh[tid]=s; __syncthreads();
    for(int o=128;o>0;o>>=1){ if(tid<o) sh[tid]+=sh[tid+o]; __syncthreads(); }
    if(tid==0) out[li]=sh[0]*inv_nd;
}

extern "C" void kernel_launch(void* const* d_in,const int* in_sizes,int n_in,
                              void* d_out,int out_size){
    const float* z=(const float*)d_in[0];
    const float* cb=(const float*)d_in[1];
    int sz0=in_sizes[0], sz1=in_sizes[1];
    if(sz0<sz1){ const float* tp=z; z=cb; cb=tp; int ts=sz0; sz0=sz1; sz1=ts; }
    float* out=(float*)d_out;
    int nrows=sz0/D, nblocks=nrows/TILE_M;

    cudaFuncSetAttribute(svq_hmma, cudaFuncAttributeMaxDynamicSharedMemorySize, SMEM_TOTAL);
    prep_cb<<<KTOT,256>>>(cb);
    svq_hmma<<<nblocks,THREADS,SMEM_TOTAL>>>(z,out);
    loss_finalize<<<1,256>>>(out,nblocks,1.0f/((float)nrows*(float)D),out_size-1);
}

// round 10
// speedup vs baseline: 1.1263x; 1.0002x over previous
#include <cuda_runtime.h>
#include <cuda_fp16.h>
#include <cstdint>

// SoftVectorQuantizer R9: R8 + exp split across MUFU/FMA pipes + h2 den accum.
// w = exp2(S - log2e||e||^2), S = (2log2e z).e; z_soft=(W E)/rowsum(W)

#define D 256
#define KTOT 1024
#define TILE_M 64
#define KC 64
#define NCH 16
#define THREADS 128
#define SCLF 2.8853900817779268f
#define LOG2E 1.4426950408889634f

#define OFF_CE   0
#define OFF_W    2048
#define OFF_DENP OFF_W
#define OFF_DEN  (OFF_W+2048)
#define OFF_RED  (OFF_W+2304)
#define OFF_Z    10240
#define OFF_EB   43008
#define SMEM_TOTAL (OFF_EB + 2*32768)   // ~106KB -> 2 CTAs/SM

#define SWZ128(o) ((o) ^ (((o) >> 3) & 0x70))

__device__ __forceinline__ uint32_t smem_u32(const void* p){
    uint32_t a; asm("{ .reg .u64 t; cvta.to.shared.u64 t, %1; cvt.u32.u64 %0, t; }":"=r"(a):"l"(p)); return a;
}
__device__ __forceinline__ __half2 h2ex2(__half2 x){
    uint32_t y, xi=*(uint32_t*)&x;
    asm("ex2.approx.f16x2 %0, %1;":"=r"(y):"r"(xi));
    return *(__half2*)&y;
}

#define CPA16(d,s) asm volatile("cp.async.cg.shared.global [%0], [%1], 16;"::"r"(d),"l"(s):"memory")
#define CPA_COMMIT() asm volatile("cp.async.commit_group;":::"memory")
#define CPA_WAIT1() asm volatile("cp.async.wait_group 1;":::"memory")
#define CPA_WAIT0() asm volatile("cp.async.wait_group 0;":::"memory")

#define LDSM4(r,a) asm volatile("ldmatrix.sync.aligned.m8n8.x4.shared.b16 {%0,%1,%2,%3}, [%4];" \
    :"=r"((r)[0]),"=r"((r)[1]),"=r"((r)[2]),"=r"((r)[3]):"r"(a))
#define LDSM4T(r,a) asm volatile("ldmatrix.sync.aligned.m8n8.x4.trans.shared.b16 {%0,%1,%2,%3}, [%4];" \
    :"=r"((r)[0]),"=r"((r)[1]),"=r"((r)[2]),"=r"((r)[3]):"r"(a))

#define MMA(dd,aa,b0,b1) asm volatile( \
    "mma.sync.aligned.m16n8k16.row.col.f32.f16.f16.f32 {%0,%1,%2,%3},{%4,%5,%6,%7},{%8,%9},{%0,%1,%2,%3};" \
    : "+f"((dd)[0]),"+f"((dd)[1]),"+f"((dd)[2]),"+f"((dd)[3]) \
    : "r"((aa)[0]),"r"((aa)[1]),"r"((aa)[2]),"r"((aa)[3]),"r"(b0),"r"(b1))
#define MMAH(dd,aa,b0,b1) asm volatile( \
    "mma.sync.aligned.m16n8k16.row.col.f16.f16.f16.f16 {%0,%1},{%2,%3,%4,%5},{%6,%7},{%0,%1};" \
    : "+r"((dd)[0]),"+r"((dd)[1]) \
    : "r"((aa)[0]),"r"((aa)[1]),"r"((aa)[2]),"r"((aa)[3]),"r"(b0),"r"(b1))

__device__ __align__(16) __half g_eh[KTOT*D];
__device__ float g_ce2[KTOT];
__device__ float g_block_loss[2048];

__global__ void prep_cb(const float* __restrict__ cb){
    int k=blockIdx.x, d=threadIdx.x;
    float v=cb[k*D+d];
    g_eh[k*D+d]=__float2half(v);
    __shared__ float sh[256];
    sh[d]=v*v; __syncthreads();
    for(int o=128;o>0;o>>=1){ if(d<o) sh[d]+=sh[d+o]; __syncthreads(); }
    if(d==0) g_ce2[k]=sh[0]*LOG2E;
}

// empty pads so ncu's "-s 5 -c 1" capture lands on svq_hmma
__global__ void ncu_pad(){}

__device__ __forceinline__ void load_chunk(uint32_t sb,int ch,int buf,int tid){
    const char* g=(const char*)g_eh + (size_t)ch*KC*D*2;
    uint32_t eb=sb+OFF_EB+buf*32768;
    #pragma unroll
    for(int i=0;i<16;i++){
        int u=i*THREADS+tid, row=u>>5, un=u&31;
        uint32_t dst=eb+(un>>3)*8192+SWZ128((uint32_t)(row*128+(un&7)*16));
        CPA16(dst, g+(size_t)row*512+un*16);
    }
}

extern __shared__ char smem[];

__global__ void __launch_bounds__(THREADS,2) svq_hmma(
    const float* __restrict__ z, float* __restrict__ out)
{
    uint32_t sb=smem_u32(smem);
    int tid=threadIdx.x, wid=tid>>5, t=tid&31;
    int mg=wid>>1, ng1=wid&1;      // GEMM1 grid 2x2 (m32 x n32)
    int ng2=wid;                   // GEMM2 grid 1x4 (m64 x n64)
    size_t rowBase=(size_t)blockIdx.x*TILE_M;

    load_chunk(sb,0,0,tid); CPA_COMMIT();
    load_chunk(sb,1,1,tid); CPA_COMMIT();

    __half* sCE=(__half*)(smem+OFF_CE);
    for(int i=tid;i<KTOT;i+=THREADS) sCE[i]=__float2half(g_ce2[i]);

    {
        const float4* zg=(const float4*)(z+rowBase*D);
        #pragma unroll
        for(int it=0;it<16;it++){
            int idx=it*THREADS+tid, r=idx>>5, q=idx&31;
            float4 a=zg[(size_t)r*64+q*2], b=zg[(size_t)r*64+q*2+1];
            __half2 h0=__floats2half2_rn(a.x*SCLF,a.y*SCLF), h1=__floats2half2_rn(a.z*SCLF,a.w*SCLF);
            __half2 h2=__floats2half2_rn(b.x*SCLF,b.y*SCLF), h3=__floats2half2_rn(b.z*SCLF,b.w*SCLF);
            uint4 u; u.x=*(uint32_t*)&h0; u.y=*(uint32_t*)&h1; u.z=*(uint32_t*)&h2; u.w=*(uint32_t*)&h3;
            *(uint4*)(smem+OFF_Z+(q>>3)*8192+SWZ128((uint32_t)(r*128+(q&7)*16)))=u;
        }
    }

    const uint32_t xv=(uint32_t)(t&7)<<4;
    const uint32_t c0=(uint32_t)(t>>4)<<4;
    uint32_t cs[4];
    #pragma unroll
    for(int k=0;k<4;k++) cs[k]=(c0+k*32)^xv;

    const uint32_t zA0=sb+OFF_Z+(uint32_t)(32*mg+(t&15))*128;
    const uint32_t xw=(uint32_t)(t>>2)<<4;

    const __half2 pc1=__float2half2_rn(0.6931472f);
    const __half2 pc2=__float2half2_rn(0.2402265f);
    const __half2 pone=__float2half2_rn(1.0f);

    float acc2[4][8][4];
    #pragma unroll
    for(int mi=0;mi<4;mi++)
        #pragma unroll
        for(int j=0;j<8;j++)
            #pragma unroll
            for(int q=0;q<4;q++) acc2[mi][j][q]=0.f;
    float den[4]={0.f,0.f,0.f,0.f};

    #pragma unroll 1
    for(int ch=0;ch<NCH;ch++){
        if(ch<NCH-1) CPA_WAIT1(); else CPA_WAIT0();
        __syncthreads();
        const uint32_t eb=sb+OFF_EB+(uint32_t)(ch&1)*32768;
        const uint32_t eB0=eb+(uint32_t)(32*ng1+(t&15))*128;

        // ---- GEMM1: S[m32 x n32], f16 acc ----
        uint32_t acc1[2][4][2];
        #pragma unroll
        for(int mi=0;mi<2;mi++)
            #pragma unroll
            for(int nj=0;nj<4;nj++){ acc1[mi][nj][0]=0u; acc1[mi][nj][1]=0u; }
        #pragma unroll
        for(int ks=0;ks<16;ks++){
            uint32_t a0[4],a1[4],b0[4],b1[4];
            uint32_t blk=(uint32_t)(ks>>2)*8192, cc=cs[ks&3];
            LDSM4(a0, zA0+blk+cc);
            LDSM4(a1, zA0+2048+blk+cc);
            LDSM4(b0, eB0+blk+cc);
            LDSM4(b1, eB0+2048+blk+cc);
            MMAH(acc1[0][0],a0,b0[0],b0[2]); MMAH(acc1[0][1],a0,b0[1],b0[3]);
            MMAH(acc1[0][2],a0,b1[0],b1[2]); MMAH(acc1[0][3],a0,b1[1],b1[3]);
            MMAH(acc1[1][0],a1,b0[0],b0[2]); MMAH(acc1[1][1],a1,b0[1],b0[3]);
            MMAH(acc1[1][2],a1,b1[0],b1[2]); MMAH(acc1[1][3],a1,b1[1],b1[3]);
        }

        // ---- epilogue: exp split MUFU/poly, den in half2, store W ----
        const __half2* ceh=(const __half2*)(smem+OFF_CE)+(ch*32)+(16*ng1)+(t&3);
        #pragma unroll
        for(int mi=0;mi<2;mi++){
            uint32_t r0=(uint32_t)(32*mg+16*mi+(t>>2));
            __half2 ds0=__float2half2_rn(0.f), ds1=__float2half2_rn(0.f);
            #pragma unroll
            for(int nj=0;nj<4;nj++){
                __half2 ce2v=ceh[nj*4];
                uint32_t s0=acc1[mi][nj][0], s1=acc1[mi][nj][1];
                __half2 d0=__hsub2(*(__half2*)&s0,ce2v), d1=__hsub2(*(__half2*)&s1,ce2v);
                __half2 w0,w1;
                if(nj&1){   // FMA-pipe quadratic exp2
                    w0=__hfma2(d0,__hfma2(pc2,d0,pc1),pone);
                    w1=__hfma2(d1,__hfma2(pc2,d1,pc1),pone);
                }else{      // MUFU
                    w0=h2ex2(d0); w1=h2ex2(d1);
                }
                ds0=__hadd2(ds0,w0); ds1=__hadd2(ds1,w1);
                uint32_t cw=((uint32_t)((32*ng1+nj*8+(t&3)*2)*2))^xw;
                *(uint32_t*)(smem+OFF_W+r0*128+cw)=*(uint32_t*)&w0;
                *(uint32_t*)(smem+OFF_W+(r0+8)*128+cw)=*(uint32_t*)&w1;
            }
            float2 f0=__half22float2(ds0), f1=__half22float2(ds1);
            den[mi*2+0]+=f0.x+f0.y; den[mi*2+1]+=f1.x+f1.y;
        }
        __syncthreads();

        // ---- GEMM2: acc2[m64 x n64] += W * E^T(block ng2) ----
        #pragma unroll
        for(int ks=0;ks<4;ks++){
            uint32_t a[4][4];
            #pragma unroll
            for(int q=0;q<4;q++)
                LDSM4(a[q], sb+OFF_W+(uint32_t)(16*q+(t&15))*128+cs[ks]);
            uint32_t eT=eb+(uint32_t)ng2*8192+(uint32_t)(ks*16+(t&15))*128;
            #pragma unroll
            for(int nt=0;nt<4;nt++){
                uint32_t bt[4];
                LDSM4T(bt, eT+cs[nt]);
                #pragma unroll
                for(int mi=0;mi<4;mi++){
                    MMA(acc2[mi][nt*2],  a[mi],bt[0],bt[1]);
                    MMA(acc2[mi][nt*2+1],a[mi],bt[2],bt[3]);
                }
            }
        }
        __syncthreads();
        if(ch<NCH-2){ load_chunk(sb,ch+2,ch&1,tid); CPA_COMMIT(); }
    }

    // ---- denominator reduce (fixed order) ----
    float* dP=(float*)(smem+OFF_DENP);
    #pragma unroll
    for(int mi=0;mi<2;mi++)
        #pragma unroll
        for(int rg=0;rg<2;rg++){
            int rr=32*mg+16*mi+8*rg+(t>>2);
            dP[rr*8+ng1*4+(t&3)]=den[mi*2+rg];
        }
    __syncthreads();
    float* dF=(float*)(smem+OFF_DEN);
    if(tid<TILE_M){
        float s=0.f;
        #pragma unroll
        for(int j=0;j<8;j++) s+=dP[tid*8+j];
        dF[tid]=s;
    }
    __syncthreads();

    // ---- normalize, write out, loss vs fp32 z ----
    float lsum=0.f;
    #pragma unroll
    for(int mi=0;mi<4;mi++){
        int r0=16*mi+(t>>2);
        float inv0=1.f/dF[r0], inv1=1.f/dF[r0+8];
        size_t g0=(rowBase+r0)*D, g1=g0+8*(size_t)D;
        #pragma unroll
        for(int j=0;j<8;j++){
            int dc=64*ng2+j*8+(t&3)*2;
            float ox0=acc2[mi][j][0]*inv0, oy0=acc2[mi][j][1]*inv0;
            float ox1=acc2[mi][j][2]*inv1, oy1=acc2[mi][j][3]*inv1;
            float2 z0=*(const float2*)(z+g0+dc);
            float2 z1=*(const float2*)(z+g1+dc);
            float d0=ox0-z0.x, d1=oy0-z0.y, d2=ox1-z1.x, d3=oy1-z1.y;
            lsum+=d0*d0+d1*d1+d2*d2+d3*d3;
            *(float2*)(out+g0+dc)=make_float2(ox0,oy0);
            *(float2*)(out+g1+dc)=make_float2(ox1,oy1);
        }
    }
    #pragma unroll
    for(int o=16;o>0;o>>=1) lsum+=__shfl_down_sync(0xffffffffu,lsum,o);
    float* sRed=(float*)(smem+OFF_RED);
    if(t==0) sRed[wid]=lsum;
    __syncthreads();
    if(tid==0){
        float s=0.f;
        #pragma unroll
        for(int w=0;w<4;w++) s+=sRed[w];
        g_block_loss[blockIdx.x]=s;
    }
}

__global__ void loss_finalize(float* __restrict__ out,int nblocks,float inv_nd,int li){
    __shared__ float sh[256];
    int tid=threadIdx.x; float s=0.f;
    for(int i=tid;i<nblocks;i+=256) s+=g_block_loss[i];
    sh[tid]=s; __syncthreads();
    for(int o=128;o>0;o>>=1){ if(tid<o) sh[tid]+=sh[tid+o]; __syncthreads(); }
    if(tid==0) out[li]=sh[0]*inv_nd;
}

extern "C" void kernel_launch(void* const* d_in,const int* in_sizes,int n_in,
                              void* d_out,int out_size){
    const float* z=(const float*)d_in[0];
    const float* cb=(const float*)d_in[1];
    int sz0=in_sizes[0], sz1=in_sizes[1];
    if(sz0<sz1){ const float* tp=z; z=cb; cb=tp; int ts=sz0; sz0=sz1; sz1=ts; }
    float* out=(float*)d_out;
    int nrows=sz0/D, nblocks=nrows/TILE_M;

    cudaFuncSetAttribute(svq_hmma, cudaFuncAttributeMaxDynamicSharedMemorySize, SMEM_TOTAL);
    prep_cb<<<KTOT,256>>>(cb);
    // pads: shift global launch index so ncu (-s 5 -c 1) captures svq_hmma
    ncu_pad<<<1,32>>>(); ncu_pad<<<1,32>>>(); ncu_pad<<<1,32>>>();
    svq_hmma<<<nblocks,THREADS,SMEM_TOTAL>>>(z,out);
    loss_finalize<<<1,256>>>(out,nblocks,1.0f/((float)nrows*(float)D),out_size-1);
}